// round 10
// baseline (speedup 1.0000x reference)
#include <cuda_runtime.h>

#ifndef EPSF
#define EPSF 1e-07f
#endif

#define NTHREADS 256
#define UNROLL   2          // pair-iterations per thread (2 boxes each)
#define MAXBLK   8192

static __device__ float        g_partials[MAXBLK];
static __device__ unsigned int g_count;   // zero at load; atomicInc wrap self-resets

// 256-bit evict-last load: two adjacent boxes per instruction
__device__ __forceinline__ void ldg2_evict_last(const float4* p, float4& a, float4& b) {
    unsigned r0, r1, r2, r3, r4, r5, r6, r7;
    asm("ld.global.L2::evict_last.v8.b32 {%0,%1,%2,%3,%4,%5,%6,%7}, [%8];"
        : "=r"(r0), "=r"(r1), "=r"(r2), "=r"(r3),
          "=r"(r4), "=r"(r5), "=r"(r6), "=r"(r7)
        : "l"(p));
    a.x = __uint_as_float(r0); a.y = __uint_as_float(r1);
    a.z = __uint_as_float(r2); a.w = __uint_as_float(r3);
    b.x = __uint_as_float(r4); b.y = __uint_as_float(r5);
    b.z = __uint_as_float(r6); b.w = __uint_as_float(r7);
}

__device__ __forceinline__ float ciou_term(float4 p, float4 t) {
    float px1 = p.x, py1 = p.y, px2 = p.z, py2 = p.w;
    float tx1 = t.x, ty1 = t.y, tx2 = t.z, ty2 = t.w;

    float iw = fmaxf(fminf(px2, tx2) - fmaxf(px1, tx1), 0.0f);
    float ih = fmaxf(fminf(py2, ty2) - fmaxf(py1, ty1), 0.0f);
    float inter = iw * ih;

    float pw = px2 - px1, ph = py2 - py1;
    float tw = tx2 - tx1, th = ty2 - ty1;

    float d_iou = pw * ph + tw * th - inter + EPSF;   // union + eps

    float dcx = 0.5f * (px1 + px2) - 0.5f * (tx1 + tx2);
    float dcy = 0.5f * (py1 + py2) - 0.5f * (ty1 + ty2);
    float center_dist_sq = dcx * dcx + dcy * dcy;

    float cw = fmaxf(px2, tx2) - fminf(px1, tx1);
    float ch = fmaxf(py2, ty2) - fminf(py1, ty1);
    float c_diag_sq = cw * cw + ch * ch + EPSF;       // eps inside bbox_iou
    float d_ctr = c_diag_sq + EPSF;                   // eps again in forward()

    float inv12 = __fdividef(1.0f, d_iou * d_ctr);    // one rcp serves two divides
    float iou         = inter * d_ctr * inv12;
    float center_term = center_dist_sq * d_iou * inv12;

    float d3 = tw + EPSF, d4 = th + EPSF;
    float inv34 = __fdividef(1.0f, d3 * d4);
    float sw = (pw - tw) * d4 * inv34;
    float sh = (ph - th) * d3 * inv34;

    return (1.0f - iou) + 2.0f * center_term + (sw * sw + sh * sh);
}

__global__ void __launch_bounds__(NTHREADS, 6)
ciou_fused_kernel(const float4* __restrict__ pred,
                  const float4* __restrict__ targ,
                  float* __restrict__ out,
                  int n) {
    const int npairs = n >> 1;
    const int stride = gridDim.x * NTHREADS;              // in pairs
    const int base   = blockIdx.x * NTHREADS + threadIdx.x;

    float local = 0.0f;

    if (base + (UNROLL - 1) * stride < npairs) {
        #pragma unroll
        for (int k = 0; k < UNROLL; k++) {
            int i = base + k * stride;                    // pair index
            float4 p0, p1, t0, t1;
            ldg2_evict_last(&pred[2 * i], p0, p1);
            ldg2_evict_last(&targ[2 * i], t0, t1);
            local += ciou_term(p0, t0);
            local += ciou_term(p1, t1);
        }
        for (int i = base + UNROLL * stride; i < npairs; i += stride) {
            float4 p0, p1, t0, t1;
            ldg2_evict_last(&pred[2 * i], p0, p1);
            ldg2_evict_last(&targ[2 * i], t0, t1);
            local += ciou_term(p0, t0);
            local += ciou_term(p1, t1);
        }
    } else {
        for (int i = base; i < npairs; i += stride) {
            float4 p0, p1, t0, t1;
            ldg2_evict_last(&pred[2 * i], p0, p1);
            ldg2_evict_last(&targ[2 * i], t0, t1);
            local += ciou_term(p0, t0);
            local += ciou_term(p1, t1);
        }
    }

    // odd-n tail (none for N=4.19M, but stay correct)
    if ((n & 1) && blockIdx.x == 0 && threadIdx.x == 0)
        local += ciou_term(pred[n - 1], targ[n - 1]);

    // intra-block reduce
    #pragma unroll
    for (int off = 16; off > 0; off >>= 1)
        local += __shfl_down_sync(0xFFFFFFFFu, local, off);

    __shared__ float warp_sums[NTHREADS / 32];
    int lane = threadIdx.x & 31;
    int wid  = threadIdx.x >> 5;
    if (lane == 0) warp_sums[wid] = local;
    __syncthreads();

    __shared__ bool amLast;
    if (threadIdx.x == 0) {
        float bsum = 0.0f;
        #pragma unroll
        for (int w = 0; w < NTHREADS / 32; w++) bsum += warp_sums[w];
        g_partials[blockIdx.x] = bsum;
        __threadfence();
        unsigned int pos = atomicInc(&g_count, gridDim.x - 1);
        amLast = (pos == gridDim.x - 1);
    }
    __syncthreads();

    if (amLast) {
        double v = 0.0;
        for (int j = threadIdx.x; j < gridDim.x; j += NTHREADS)
            v += (double)g_partials[j];
        #pragma unroll
        for (int off = 16; off > 0; off >>= 1)
            v += __shfl_down_sync(0xFFFFFFFFu, v, off);

        __shared__ double dsums[NTHREADS / 32];
        if (lane == 0) dsums[wid] = v;
        __syncthreads();
        if (threadIdx.x == 0) {
            double tot = 0.0;
            #pragma unroll
            for (int w = 0; w < NTHREADS / 32; w++) tot += dsums[w];
            out[0] = (float)(tot / (double)n);
        }
    }
}

extern "C" void kernel_launch(void* const* d_in, const int* in_sizes, int n_in,
                              void* d_out, int out_size) {
    const float4* pred = (const float4*)d_in[0];
    const float4* targ = (const float4*)d_in[1];
    int n = in_sizes[0] / 4;   // floats -> boxes
    int npairs = n >> 1;

    int blocks = (npairs + NTHREADS * UNROLL - 1) / (NTHREADS * UNROLL);
    if (blocks > MAXBLK) blocks = MAXBLK;
    if (blocks < 1) blocks = 1;

    ciou_fused_kernel<<<blocks, NTHREADS>>>(pred, targ, (float*)d_out, n);
}

// round 11
// speedup vs baseline: 1.0045x; 1.0045x over previous
#include <cuda_runtime.h>

#ifndef EPSF
#define EPSF 1e-07f
#endif

#define NTHREADS 256
#define UNROLL   2          // pair-iterations per thread (2 boxes each = 4 boxes)
#define MAXBLK   8192

static __device__ float        g_partials[MAXBLK];
static __device__ unsigned int g_count;   // zero at load; atomicInc wrap self-resets

// 256-bit load: two adjacent boxes per instruction (plain caching)
__device__ __forceinline__ void ldg2(const float4* p, float4& a, float4& b) {
    unsigned r0, r1, r2, r3, r4, r5, r6, r7;
    asm("ld.global.v8.b32 {%0,%1,%2,%3,%4,%5,%6,%7}, [%8];"
        : "=r"(r0), "=r"(r1), "=r"(r2), "=r"(r3),
          "=r"(r4), "=r"(r5), "=r"(r6), "=r"(r7)
        : "l"(p));
    a.x = __uint_as_float(r0); a.y = __uint_as_float(r1);
    a.z = __uint_as_float(r2); a.w = __uint_as_float(r3);
    b.x = __uint_as_float(r4); b.y = __uint_as_float(r5);
    b.z = __uint_as_float(r6); b.w = __uint_as_float(r7);
}

__device__ __forceinline__ float ciou_term(float4 p, float4 t) {
    float px1 = p.x, py1 = p.y, px2 = p.z, py2 = p.w;
    float tx1 = t.x, ty1 = t.y, tx2 = t.z, ty2 = t.w;

    float iw = fmaxf(fminf(px2, tx2) - fmaxf(px1, tx1), 0.0f);
    float ih = fmaxf(fminf(py2, ty2) - fmaxf(py1, ty1), 0.0f);
    float inter = iw * ih;

    float pw = px2 - px1, ph = py2 - py1;
    float tw = tx2 - tx1, th = ty2 - ty1;

    float d_iou = pw * ph + tw * th - inter + EPSF;   // union + eps

    float dcx = 0.5f * (px1 + px2) - 0.5f * (tx1 + tx2);
    float dcy = 0.5f * (py1 + py2) - 0.5f * (ty1 + ty2);
    float center_dist_sq = dcx * dcx + dcy * dcy;

    float cw = fmaxf(px2, tx2) - fminf(px1, tx1);
    float ch = fmaxf(py2, ty2) - fminf(py1, ty1);
    float c_diag_sq = cw * cw + ch * ch + EPSF;       // eps inside bbox_iou
    float d_ctr = c_diag_sq + EPSF;                   // eps again in forward()

    float inv12 = __fdividef(1.0f, d_iou * d_ctr);    // one rcp serves two divides
    float iou         = inter * d_ctr * inv12;
    float center_term = center_dist_sq * d_iou * inv12;

    float d3 = tw + EPSF, d4 = th + EPSF;
    float inv34 = __fdividef(1.0f, d3 * d4);
    float sw = (pw - tw) * d4 * inv34;
    float sh = (ph - th) * d3 * inv34;

    return (1.0f - iou) + 2.0f * center_term + (sw * sw + sh * sh);
}

__global__ void __launch_bounds__(NTHREADS, 6)
ciou_fused_kernel(const float4* __restrict__ pred,
                  const float4* __restrict__ targ,
                  float* __restrict__ out,
                  int n) {
    const int npairs = n >> 1;
    const int stride = gridDim.x * NTHREADS;              // in pairs
    const int base   = blockIdx.x * NTHREADS + threadIdx.x;

    float local = 0.0f;

    if (base + (UNROLL - 1) * stride < npairs) {
        #pragma unroll
        for (int k = 0; k < UNROLL; k++) {
            int i = base + k * stride;                    // pair index
            float4 p0, p1, t0, t1;
            ldg2(&pred[2 * i], p0, p1);
            ldg2(&targ[2 * i], t0, t1);
            local += ciou_term(p0, t0);
            local += ciou_term(p1, t1);
        }
        for (int i = base + UNROLL * stride; i < npairs; i += stride) {
            float4 p0, p1, t0, t1;
            ldg2(&pred[2 * i], p0, p1);
            ldg2(&targ[2 * i], t0, t1);
            local += ciou_term(p0, t0);
            local += ciou_term(p1, t1);
        }
    } else {
        for (int i = base; i < npairs; i += stride) {
            float4 p0, p1, t0, t1;
            ldg2(&pred[2 * i], p0, p1);
            ldg2(&targ[2 * i], t0, t1);
            local += ciou_term(p0, t0);
            local += ciou_term(p1, t1);
        }
    }

    // odd-n tail (none for N=4.19M, but stay correct)
    if ((n & 1) && blockIdx.x == 0 && threadIdx.x == 0)
        local += ciou_term(pred[n - 1], targ[n - 1]);

    // intra-block reduce
    #pragma unroll
    for (int off = 16; off > 0; off >>= 1)
        local += __shfl_down_sync(0xFFFFFFFFu, local, off);

    __shared__ float warp_sums[NTHREADS / 32];
    int lane = threadIdx.x & 31;
    int wid  = threadIdx.x >> 5;
    if (lane == 0) warp_sums[wid] = local;
    __syncthreads();

    __shared__ bool amLast;
    if (threadIdx.x == 0) {
        float bsum = 0.0f;
        #pragma unroll
        for (int w = 0; w < NTHREADS / 32; w++) bsum += warp_sums[w];
        g_partials[blockIdx.x] = bsum;
        __threadfence();
        unsigned int pos = atomicInc(&g_count, gridDim.x - 1);
        amLast = (pos == gridDim.x - 1);
    }
    __syncthreads();

    if (amLast) {
        double v = 0.0;
        for (int j = threadIdx.x; j < gridDim.x; j += NTHREADS)
            v += (double)g_partials[j];
        #pragma unroll
        for (int off = 16; off > 0; off >>= 1)
            v += __shfl_down_sync(0xFFFFFFFFu, v, off);

        __shared__ double dsums[NTHREADS / 32];
        if (lane == 0) dsums[wid] = v;
        __syncthreads();
        if (threadIdx.x == 0) {
            double tot = 0.0;
            #pragma unroll
            for (int w = 0; w < NTHREADS / 32; w++) tot += dsums[w];
            out[0] = (float)(tot / (double)n);
        }
    }
}

extern "C" void kernel_launch(void* const* d_in, const int* in_sizes, int n_in,
                              void* d_out, int out_size) {
    const float4* pred = (const float4*)d_in[0];
    const float4* targ = (const float4*)d_in[1];
    int n = in_sizes[0] / 4;   // floats -> boxes
    int npairs = n >> 1;

    int blocks = (npairs + NTHREADS * UNROLL - 1) / (NTHREADS * UNROLL);
    if (blocks > MAXBLK) blocks = MAXBLK;
    if (blocks < 1) blocks = 1;

    ciou_fused_kernel<<<blocks, NTHREADS>>>(pred, targ, (float*)d_out, n);
}